// round 9
// baseline (speedup 1.0000x reference)
#include <cuda_runtime.h>
#include <cstdint>

// BidirectionalSoftmax: B=8, L1=L2=2048, TAU=0.5, EPS=1e-8
// No-max softmax: e = exp2(sim*(1/TAU)*log2 e); out = sqrt(EPS + e*e*irs*ics)
//
//   k_colstats : uniform AND parallel: 1024 CTAs (128 slabs x 8 b).
//                Thread t covers cols {4t, 1024+4t}; CTA covers rows
//                r = slab + 128k (nk = 8..16, uniform +-1 within a batch).
//   k_merge    : fold 128 slab partials -> 1/col_sum
//   k_out      : proven block-per-row + streaming cache hints (unchanged from
//                R7 win: ~34us).

#define NB    8
#define NL    2048
#define NSLAB 128
#define SCALEV 2.8853900817779268f    /* (1/0.5) * log2(e) */
#define EPSV  1e-8f

__device__ float g_cps[NB * NSLAB * NL];  // partial col sums of exp2(y)
__device__ float g_ics[NB * NL];          // 1/col_sum

__device__ __forceinline__ float ex2f(float x) {
    float r; asm("ex2.approx.f32 %0, %1;" : "=f"(r) : "f"(x)); return r;
}
__device__ __forceinline__ float sqrtap(float x) {
    float r; asm("sqrt.approx.f32 %0, %1;" : "=f"(r) : "f"(x)); return r;
}
__device__ __forceinline__ float4 ldcs4(const float4* p) {
    float4 v;
    asm volatile("ld.global.cs.v4.f32 {%0,%1,%2,%3}, [%4];"
                 : "=f"(v.x), "=f"(v.y), "=f"(v.z), "=f"(v.w) : "l"(p));
    return v;
}
__device__ __forceinline__ void stcs4(float4* p, float4 v) {
    asm volatile("st.global.cs.v4.f32 [%0], {%1,%2,%3,%4};"
                 :: "l"(p), "f"(v.x), "f"(v.y), "f"(v.z), "f"(v.w) : "memory");
}

// ---------------------------------------------------------------------------
// Pass 1: column sum partials, uniform CTAs. grid=(128,8), block=256.
// Thread t: cols [4t,4t+4) (A, always valid: len2>=1024) and [1024+4t,..) (B).
// CTA slab: rows slab, slab+128, ..., nk rows total (len1>=1024 -> nk>=8).
// ---------------------------------------------------------------------------
__global__ void __launch_bounds__(256) k_colstats(const float* __restrict__ sim,
                                                  const int*   __restrict__ len) {
    int slab = blockIdx.x, b = blockIdx.y;
    int t = threadIdx.x;
    int len1 = __ldg(&len[2 * b]);
    int len2 = __ldg(&len[2 * b + 1]);

    int nvB = len2 - (1024 + 4 * t);
    bool wB = nvB > 0, k1 = nvB > 1, k2 = nvB > 2, k3 = nvB > 3;

    int nk = (len1 - slab + 127) >> 7;         // valid strided rows (8..16)

    float a0 = 0.f, a1 = 0.f, a2 = 0.f, a3 = 0.f;
    float c0 = 0.f, c1 = 0.f, c2 = 0.f, c3 = 0.f;

    const float4* p = reinterpret_cast<const float4*>(sim)
                    + ((size_t)b << 20) + ((size_t)slab << 9) + t;
    const float4 z4 = make_float4(0.f, 0.f, 0.f, 0.f);

#define PROC(vA, vB)                                   \
    do {                                               \
        a0 += ex2f((vA).x * SCALEV);                   \
        a1 += ex2f((vA).y * SCALEV);                   \
        a2 += ex2f((vA).z * SCALEV);                   \
        a3 += ex2f((vA).w * SCALEV);                   \
        c0 += wB ? ex2f((vB).x * SCALEV) : 0.f;        \
        c1 += k1 ? ex2f((vB).y * SCALEV) : 0.f;        \
        c2 += k2 ? ex2f((vB).z * SCALEV) : 0.f;        \
        c3 += k3 ? ex2f((vB).w * SCALEV) : 0.f;        \
    } while (0)

    // row stride 128 rows = 128*512 float4
    int k = 0;
    for (; k + 4 <= nk; k += 4) {
        float4 vA[4], vB[4];
#pragma unroll
        for (int u = 0; u < 4; u++) vA[u] = p[(size_t)u * 65536];
#pragma unroll
        for (int u = 0; u < 4; u++) vB[u] = wB ? p[(size_t)u * 65536 + 256] : z4;
        p += (size_t)4 * 65536;
#pragma unroll
        for (int u = 0; u < 4; u++) PROC(vA[u], vB[u]);
    }
    for (; k < nk; k++) {
        float4 vA = p[0];
        float4 vB = wB ? p[256] : z4;
        p += 65536;
        PROC(vA, vB);
    }
#undef PROC

    size_t base = (size_t)(b * NSLAB + slab) << 11;
    *reinterpret_cast<float4*>(&g_cps[base + 4 * t])        = make_float4(a0, a1, a2, a3);
    *reinterpret_cast<float4*>(&g_cps[base + 1024 + 4 * t]) = make_float4(c0, c1, c2, c3);
}

// ---------------------------------------------------------------------------
// Pass 1b: fold 128 slab partials per (batch, column) -> 1/col_sum.
// ---------------------------------------------------------------------------
__global__ void __launch_bounds__(256) k_merge() {
    int idx = blockIdx.x * 256 + threadIdx.x;     // b*NL + j
    int b = idx >> 11, j = idx & (NL - 1);

    float acc = 0.f;
#pragma unroll 8
    for (int s = 0; s < NSLAB; s++)
        acc += g_cps[((size_t)(b * NSLAB + s) << 11) + j];
    g_ics[idx] = acc > 0.f ? (1.0f / acc) : 0.f;
}

// ---------------------------------------------------------------------------
// Pass 2: proven block-per-row + streaming cache hints (unchanged).
// ---------------------------------------------------------------------------
__global__ void __launch_bounds__(256) k_out(const float* __restrict__ sim,
                                             const int*   __restrict__ len,
                                             float*       __restrict__ out) {
    int row = blockIdx.x;                 // 0 .. NB*NL-1
    int b = row >> 11, i = row & (NL - 1);
    int t = threadIdx.x;
    size_t base = ((size_t)b << 22) + ((size_t)i << 11);
    float4* orow = reinterpret_cast<float4*>(out + base);

    int len1 = __ldg(&len[2 * b]);
    if (i >= len1) {
        float4 z = make_float4(0.f, 0.f, 0.f, 0.f);
        stcs4(&orow[t], z);
        stcs4(&orow[256 + t], z);
        return;
    }
    int len2 = __ldg(&len[2 * b + 1]);
    const float4* prow = reinterpret_cast<const float4*>(sim + base);

    float4 vA = ldcs4(&prow[t]);
    float eA0 = ex2f(vA.x * SCALEV), eA1 = ex2f(vA.y * SCALEV);
    float eA2 = ex2f(vA.z * SCALEV), eA3 = ex2f(vA.w * SCALEV);

    int nvB = len2 - (1024 + 4 * t);
    float eB0 = 0.f, eB1 = 0.f, eB2 = 0.f, eB3 = 0.f;
    if (nvB > 0) {
        float4 vB = ldcs4(&prow[256 + t]);
        eB0 = ex2f(vB.x * SCALEV);
        if (nvB > 1) eB1 = ex2f(vB.y * SCALEV);
        if (nvB > 2) eB2 = ex2f(vB.z * SCALEV);
        if (nvB > 3) eB3 = ex2f(vB.w * SCALEV);
    }

    // --- block reduce row sum ---
    __shared__ float ssm[8];
    int lane = t & 31, wid = t >> 5;
    float s = (eA0 + eA1) + (eA2 + eA3) + (eB0 + eB1) + (eB2 + eB3);
#pragma unroll
    for (int o = 16; o; o >>= 1) s += __shfl_xor_sync(0xffffffffu, s, o);
    if (lane == 0) ssm[wid] = s;
    __syncthreads();
    float rs = (ssm[0] + ssm[1]) + (ssm[2] + ssm[3])
             + (ssm[4] + ssm[5]) + (ssm[6] + ssm[7]);
    float inv_rs = 1.0f / rs;

    const float4* gc = reinterpret_cast<const float4*>(g_ics + ((size_t)b << 11));

    // --- chunk A output (always fully valid) ---
    float4 icA = __ldg(&gc[t]);
    float4 oA;
    oA.x = sqrtap(fmaf(eA0 * eA0 * inv_rs, icA.x, EPSV));
    oA.y = sqrtap(fmaf(eA1 * eA1 * inv_rs, icA.y, EPSV));
    oA.z = sqrtap(fmaf(eA2 * eA2 * inv_rs, icA.z, EPSV));
    oA.w = sqrtap(fmaf(eA3 * eA3 * inv_rs, icA.w, EPSV));
    stcs4(&orow[t], oA);

    // --- chunk B output (masked -> exact zeros outside valid region) ---
    float4 oB = make_float4(0.f, 0.f, 0.f, 0.f);
    if (nvB > 0) {
        float4 icB = __ldg(&gc[256 + t]);
        oB.x = sqrtap(fmaf(eB0 * eB0 * inv_rs, icB.x, EPSV));
        if (nvB > 1) oB.y = sqrtap(fmaf(eB1 * eB1 * inv_rs, icB.y, EPSV));
        if (nvB > 2) oB.z = sqrtap(fmaf(eB2 * eB2 * inv_rs, icB.z, EPSV));
        if (nvB > 3) oB.w = sqrtap(fmaf(eB3 * eB3 * inv_rs, icB.w, EPSV));
    }
    stcs4(&orow[256 + t], oB);
}

// ---------------------------------------------------------------------------
extern "C" void kernel_launch(void* const* d_in, const int* in_sizes, int n_in,
                              void* d_out, int out_size) {
    const float* sim = (const float*)d_in[0];
    const int*   len = (const int*)d_in[1];
    if (n_in >= 2 && in_sizes[0] == 16) {   // defensive: swapped order
        sim = (const float*)d_in[1];
        len = (const int*)d_in[0];
    }
    float* out = (float*)d_out;

    dim3 g1(NSLAB, NB);                       // 1024 uniform CTAs
    k_colstats<<<g1, 256>>>(sim, len);
    k_merge<<<(NB * NL) / 256, 256>>>();      // 64 CTAs
    k_out<<<NB * NL, 256>>>(sim, len, out);   // 16384 CTAs
}

// round 11
// speedup vs baseline: 1.0920x; 1.0920x over previous
#include <cuda_runtime.h>
#include <cstdint>

// BidirectionalSoftmax: B=8, L1=L2=2048, TAU=0.5, EPS=1e-8
// No-max softmax: e = exp2(sim*(1/TAU)*log2 e); out = sqrt(EPS + e*e*irs*ics)
//
// Best proven components, one change from R7 (57.9us):
//   k_colstats : R3 structure, PROVEN 18.3us. grid (2 col-groups, 64 slabs, 8 b)
//                = 1024 CTAs, slab = 32 contiguous rows, unroll-8 float4, no smem.
//   k_merge    : fold 64 slab partials -> 1/col_sum (~1.5us)
//   k_out      : R7 block-per-row + .cs streaming hints, PROVEN ~35us. UNCHANGED.

#define NB    8
#define NL    2048
#define NSLAB 64
#define RPS   32                      /* rows per slab */
#define SCALEV 2.8853900817779268f    /* (1/0.5) * log2(e) */
#define EPSV  1e-8f

__device__ float g_cps[NB * NSLAB * NL];  // partial col sums of exp2(y)
__device__ float g_ics[NB * NL];          // 1/col_sum

__device__ __forceinline__ float ex2f(float x) {
    float r; asm("ex2.approx.f32 %0, %1;" : "=f"(r) : "f"(x)); return r;
}
__device__ __forceinline__ float sqrtap(float x) {
    float r; asm("sqrt.approx.f32 %0, %1;" : "=f"(r) : "f"(x)); return r;
}
__device__ __forceinline__ float4 ldcs4(const float4* p) {
    float4 v;
    asm volatile("ld.global.cs.v4.f32 {%0,%1,%2,%3}, [%4];"
                 : "=f"(v.x), "=f"(v.y), "=f"(v.z), "=f"(v.w) : "l"(p));
    return v;
}
__device__ __forceinline__ void stcs4(float4* p, float4 v) {
    asm volatile("st.global.cs.v4.f32 [%0], {%1,%2,%3,%4};"
                 :: "l"(p), "f"(v.x), "f"(v.y), "f"(v.z), "f"(v.w) : "memory");
}

// ---------------------------------------------------------------------------
// Pass 1: column sum partials. grid=(2, 64, 8), block=256.  [PROVEN 18.3us]
// Thread owns 4 consecutive columns; slab = 32 contiguous rows; unroll 8.
// ---------------------------------------------------------------------------
__global__ void __launch_bounds__(256) k_colstats(const float* __restrict__ sim,
                                                  const int*   __restrict__ len) {
    int b = blockIdx.z, slab = blockIdx.y, grp = blockIdx.x;
    int t = threadIdx.x;
    int col = grp * 1024 + t * 4;
    int len1 = __ldg(&len[2 * b]);
    int len2 = __ldg(&len[2 * b + 1]);
    int r0 = slab * RPS;
    int rend = min(r0 + RPS, len1);

    float s0 = 0.f, s1 = 0.f, s2 = 0.f, s3 = 0.f;

    if (col < len2 && r0 < rend) {
        int nv = len2 - col;            // >= 1
        bool k1 = nv > 1, k2 = nv > 2, k3 = nv > 3;
        const float4* p = reinterpret_cast<const float4*>(sim)
                        + ((size_t)b << 20) + ((size_t)r0 << 9) + (col >> 2);
        int n = rend - r0;

#define PROC(v)                                        \
        do {                                           \
            s0 += ex2f((v).x * SCALEV);                \
            s1 += k1 ? ex2f((v).y * SCALEV) : 0.f;     \
            s2 += k2 ? ex2f((v).z * SCALEV) : 0.f;     \
            s3 += k3 ? ex2f((v).w * SCALEV) : 0.f;     \
        } while (0)

        int r = 0;
        for (; r + 8 <= n; r += 8) {
            float4 v[8];
#pragma unroll
            for (int u = 0; u < 8; u++) v[u] = p[u * 512];
            p += 8 * 512;
#pragma unroll
            for (int u = 0; u < 8; u++) PROC(v[u]);
        }
        for (; r < n; r++) { float4 v = p[0]; p += 512; PROC(v); }
#undef PROC
    }

    size_t idx = ((size_t)(b * NSLAB + slab) << 11) + col;
    *reinterpret_cast<float4*>(&g_cps[idx]) = make_float4(s0, s1, s2, s3);
}

// ---------------------------------------------------------------------------
// Pass 1b: fold 64 slab partials per (batch, column) -> 1/col_sum.
// ---------------------------------------------------------------------------
__global__ void __launch_bounds__(256) k_merge() {
    int idx = blockIdx.x * 256 + threadIdx.x;     // b*NL + j
    int b = idx >> 11, j = idx & (NL - 1);

    float acc = 0.f;
#pragma unroll
    for (int s = 0; s < NSLAB; s++)
        acc += g_cps[((size_t)(b * NSLAB + s) << 11) + j];
    g_ics[idx] = acc > 0.f ? (1.0f / acc) : 0.f;
}

// ---------------------------------------------------------------------------
// Pass 2: block-per-row + streaming cache hints. [PROVEN ~35us, UNCHANGED]
// ---------------------------------------------------------------------------
__global__ void __launch_bounds__(256) k_out(const float* __restrict__ sim,
                                             const int*   __restrict__ len,
                                             float*       __restrict__ out) {
    int row = blockIdx.x;                 // 0 .. NB*NL-1
    int b = row >> 11, i = row & (NL - 1);
    int t = threadIdx.x;
    size_t base = ((size_t)b << 22) + ((size_t)i << 11);
    float4* orow = reinterpret_cast<float4*>(out + base);

    int len1 = __ldg(&len[2 * b]);
    if (i >= len1) {
        float4 z = make_float4(0.f, 0.f, 0.f, 0.f);
        stcs4(&orow[t], z);
        stcs4(&orow[256 + t], z);
        return;
    }
    int len2 = __ldg(&len[2 * b + 1]);
    const float4* prow = reinterpret_cast<const float4*>(sim + base);

    float4 vA = ldcs4(&prow[t]);
    float eA0 = ex2f(vA.x * SCALEV), eA1 = ex2f(vA.y * SCALEV);
    float eA2 = ex2f(vA.z * SCALEV), eA3 = ex2f(vA.w * SCALEV);

    int nvB = len2 - (1024 + 4 * t);
    float eB0 = 0.f, eB1 = 0.f, eB2 = 0.f, eB3 = 0.f;
    if (nvB > 0) {
        float4 vB = ldcs4(&prow[256 + t]);
        eB0 = ex2f(vB.x * SCALEV);
        if (nvB > 1) eB1 = ex2f(vB.y * SCALEV);
        if (nvB > 2) eB2 = ex2f(vB.z * SCALEV);
        if (nvB > 3) eB3 = ex2f(vB.w * SCALEV);
    }

    // --- block reduce row sum ---
    __shared__ float ssm[8];
    int lane = t & 31, wid = t >> 5;
    float s = (eA0 + eA1) + (eA2 + eA3) + (eB0 + eB1) + (eB2 + eB3);
#pragma unroll
    for (int o = 16; o; o >>= 1) s += __shfl_xor_sync(0xffffffffu, s, o);
    if (lane == 0) ssm[wid] = s;
    __syncthreads();
    float rs = (ssm[0] + ssm[1]) + (ssm[2] + ssm[3])
             + (ssm[4] + ssm[5]) + (ssm[6] + ssm[7]);
    float inv_rs = 1.0f / rs;

    const float4* gc = reinterpret_cast<const float4*>(g_ics + ((size_t)b << 11));

    // --- chunk A output (always fully valid) ---
    float4 icA = __ldg(&gc[t]);
    float4 oA;
    oA.x = sqrtap(fmaf(eA0 * eA0 * inv_rs, icA.x, EPSV));
    oA.y = sqrtap(fmaf(eA1 * eA1 * inv_rs, icA.y, EPSV));
    oA.z = sqrtap(fmaf(eA2 * eA2 * inv_rs, icA.z, EPSV));
    oA.w = sqrtap(fmaf(eA3 * eA3 * inv_rs, icA.w, EPSV));
    stcs4(&orow[t], oA);

    // --- chunk B output (masked -> exact zeros outside valid region) ---
    float4 oB = make_float4(0.f, 0.f, 0.f, 0.f);
    if (nvB > 0) {
        float4 icB = __ldg(&gc[256 + t]);
        oB.x = sqrtap(fmaf(eB0 * eB0 * inv_rs, icB.x, EPSV));
        if (nvB > 1) oB.y = sqrtap(fmaf(eB1 * eB1 * inv_rs, icB.y, EPSV));
        if (nvB > 2) oB.z = sqrtap(fmaf(eB2 * eB2 * inv_rs, icB.z, EPSV));
        if (nvB > 3) oB.w = sqrtap(fmaf(eB3 * eB3 * inv_rs, icB.w, EPSV));
    }
    stcs4(&orow[256 + t], oB);
}

// ---------------------------------------------------------------------------
extern "C" void kernel_launch(void* const* d_in, const int* in_sizes, int n_in,
                              void* d_out, int out_size) {
    const float* sim = (const float*)d_in[0];
    const int*   len = (const int*)d_in[1];
    if (n_in >= 2 && in_sizes[0] == 16) {   // defensive: swapped order
        sim = (const float*)d_in[1];
        len = (const int*)d_in[0];
    }
    float* out = (float*)d_out;

    dim3 g1(2, NSLAB, NB);                    // 1024 CTAs
    k_colstats<<<g1, 256>>>(sim, len);
    k_merge<<<(NB * NL) / 256, 256>>>();      // 64 CTAs
    k_out<<<NB * NL, 256>>>(sim, len, out);   // 16384 CTAs
}